// round 7
// baseline (speedup 1.0000x reference)
#include <cuda_runtime.h>
#include <math.h>

// Problem constants
constexpr int Bc = 8;
constexpr int Cc = 64;
constexpr int Nc = 4096;
constexpr int Kc = 20;
constexpr int Oc = 64;
constexpr float BN_EPS = 1e-5f;
constexpr float NEG_SLOPE = 0.2f;
constexpr float FLT_BIG = 3.4e38f;

constexpr int TI = 256;      // queries per block
constexpr int TJ = 128;      // candidate tile size
constexpr int RP = 260;      // padded row stride in floats (all shared tiles)
constexpr int NT = 512;      // threads per block (knn)

// -------------------- device scratch (no allocations allowed) --------------------
__device__ float  g_xx[Bc * Nc];            // squared norms
__device__ int    g_idx[Bc * Nc * Kc];      // knn indices
__device__ float  g_P[Bc * Nc * Oc];        // W1 . x_j projection
__device__ float  g_Q[Bc * Nc * Oc];        // (W2-W1) . x_i projection
__device__ float  g_mx[Bc * Nc * Oc];       // max_k h
__device__ float  g_mn[Bc * Nc * Oc];       // min_k h
__device__ double g_sum[Oc];
__device__ double g_sumsq[Oc];
__device__ float  g_scale[Oc];
__device__ float  g_shift[Oc];
__device__ float  g_W1t[Cc * Oc];
__device__ float  g_Wdt[Cc * Oc];

// -------------------- f32x2 packed helpers --------------------
typedef unsigned long long u64;
typedef unsigned int u32;
__device__ __forceinline__ u64 dup2(float v) {
    u64 r; asm("mov.b64 %0, {%1, %1};" : "=l"(r) : "f"(v)); return r;
}
__device__ __forceinline__ void ffma2(u64& d, u64 a, u64 b) {
    asm("fma.rn.f32x2 %0, %1, %2, %0;" : "+l"(d) : "l"(a), "l"(b));
}
__device__ __forceinline__ u64 fma2o(u64 a, u64 b, u64 c) {
    u64 r; asm("fma.rn.f32x2 %0, %1, %2, %3;" : "=l"(r) : "l"(a), "l"(b), "l"(c));
    return r;
}
__device__ __forceinline__ u64 add2(u64 a, u64 b) {
    u64 r; asm("add.rn.f32x2 %0, %1, %2;" : "=l"(r) : "l"(a), "l"(b));
    return r;
}
// orderable float mapping: monotonic uint32 key (handles negatives)
__device__ __forceinline__ u32 ordf(float f) {
    u32 u = __float_as_uint(f);
    return (u & 0x80000000u) ? ~u : (u | 0x80000000u);
}

constexpr u64 KEY_MAX = 0xFFFFFFFFFFFFFFFFull;

// -------------------- kernel: squared norms --------------------
__global__ void k_xx(const float* __restrict__ x) {
    int t = blockIdx.x * blockDim.x + threadIdx.x;    // over B*N
    int b = t >> 12;
    int n = t & (Nc - 1);
    const float* xb = x + (size_t)b * Cc * Nc + n;
    float s = 0.f;
#pragma unroll
    for (int c = 0; c < Cc; ++c) {
        float v = xb[c * Nc];
        s = fmaf(v, v, s);
    }
    g_xx[t] = s;
}

// -------------------- kernel: prep W transposes + zero stats --------------------
__global__ void k_prep(const float* __restrict__ W) {
    int t = blockIdx.x * blockDim.x + threadIdx.x;
    if (t < Cc * Oc) {
        int c = t & 63;
        int o = t >> 6;
        float w1 = W[o * (2 * Cc) + c];
        float w2 = W[o * (2 * Cc) + Cc + c];
        g_W1t[c * Oc + o] = w1;
        g_Wdt[c * Oc + o] = w2 - w1;
    }
    if (blockIdx.x == 0 && t < Oc) {
        g_sum[t] = 0.0;
        g_sumsq[t] = 0.0;
    }
}

// -------------------- kernel: P and Q projections --------------------
__global__ void __launch_bounds__(256) k_pq(const float* __restrict__ x) {
    int b  = blockIdx.y;
    int n0 = blockIdx.x * 32;
    int o  = threadIdx.x & 63;
    int gg = threadIdx.x >> 6;
    __shared__ float xs[Cc][36];

    for (int t = threadIdx.x; t < Cc * 32; t += 256) {
        int nn = t & 31;
        int c  = t >> 5;
        xs[c][nn] = x[(size_t)b * Cc * Nc + c * Nc + n0 + nn];
    }
    __syncthreads();

    float ap[8], aq[8];
#pragma unroll
    for (int r = 0; r < 8; ++r) { ap[r] = 0.f; aq[r] = 0.f; }
    const int nbase = gg * 8;

#pragma unroll 8
    for (int c = 0; c < Cc; ++c) {
        float w1 = __ldg(&g_W1t[c * Oc + o]);
        float wd = __ldg(&g_Wdt[c * Oc + o]);
        float4 v0 = *(const float4*)&xs[c][nbase];
        float4 v1 = *(const float4*)&xs[c][nbase + 4];
        ap[0] = fmaf(w1, v0.x, ap[0]); aq[0] = fmaf(wd, v0.x, aq[0]);
        ap[1] = fmaf(w1, v0.y, ap[1]); aq[1] = fmaf(wd, v0.y, aq[1]);
        ap[2] = fmaf(w1, v0.z, ap[2]); aq[2] = fmaf(wd, v0.z, aq[2]);
        ap[3] = fmaf(w1, v0.w, ap[3]); aq[3] = fmaf(wd, v0.w, aq[3]);
        ap[4] = fmaf(w1, v1.x, ap[4]); aq[4] = fmaf(wd, v1.x, aq[4]);
        ap[5] = fmaf(w1, v1.y, ap[5]); aq[5] = fmaf(wd, v1.y, aq[5]);
        ap[6] = fmaf(w1, v1.z, ap[6]); aq[6] = fmaf(wd, v1.z, aq[6]);
        ap[7] = fmaf(w1, v1.w, ap[7]); aq[7] = fmaf(wd, v1.w, aq[7]);
    }

    int row0 = b * Nc + n0 + nbase;
#pragma unroll
    for (int r = 0; r < 8; ++r) {
        g_P[(size_t)(row0 + r) * Oc + o] = ap[r];
        g_Q[(size_t)(row0 + r) * Oc + o] = aq[r];
    }
}

// -------------------- kernel: GEMM-tiled KNN v6 --------------------
// grid = (N/256, B) = 128 blocks, block = 512, smem ~196 KB (1 block/SM, 16 warps).
// Block tile 256i x 128j. Thread (ti=tid&31, tj=tid>>5) owns 8i x 8j:
//   i = {ti*4+0..3, 128+ti*4+0..3}  (two conflict-free LDS.128 A fragments)
//   j = tj*8..tj*8+7                 (warp-uniform -> broadcast B reads)
// B stored DUPLICATED in shared (Bs2[c][2j]=Bs2[c][2j+1]=B[c][j]) so packed
// f32x2 operands come straight from LDS -> zero dup-MOVs, 32 FFMA2/c-step.
// Distances scanned in two 64-j rounds per tile via Ds[64][RP]; per-thread
// top-K kept in LOCAL memory as u64 keys (ord(dist)<<32|idx), dumped to
// shared at the end for the per-query 2-way merge.
__global__ void __launch_bounds__(NT) k_knn6(const float* __restrict__ x) {
    extern __shared__ float sm[];
    float* As   = sm;                    // [Cc][RP]  (row=c, col=i 0..255)
    float* Bs2  = As + Cc * RP;          // [Cc][RP]  (row=c, col=2j dup, 0..255)
    float* Ds   = Bs2 + Cc * RP;         // [64][RP]  (row=j-local, col=i)
    float* sxxi = Ds + 64 * RP;          // [256]
    float* sxxj = sxxi + 256;            // [128]
    u64*   dump = (u64*)sm;              // reuses As/Bs2 space at the end

    const int tid = threadIdx.x;
    const int b   = blockIdx.y;
    const int i0  = blockIdx.x * TI;
    const float* xb = x + (size_t)b * Cc * Nc;

    const int ti = tid & 31;      // i-group
    const int tj = tid >> 5;      // j-group (0..15), warp-uniform
    const int qi = tid & 255;     // scan query
    const int qh = tid >> 8;      // scan half (0/1)

    // load A tile: As[c][ii] = x[b][c][i0+ii]
    {
        int col = (tid & 63) * 4;
        int cb  = tid >> 6;
#pragma unroll
        for (int cc = 0; cc < 8; ++cc) {
            int c = cb + cc * 8;
            float4 v = *(const float4*)&xb[(size_t)c * Nc + i0 + col];
            *(float4*)&As[c * RP + col] = v;
        }
    }
    if (tid < 256) sxxi[tid] = g_xx[b * Nc + i0 + tid];

    // per-thread top-K in local memory
    u64 lk[Kc];
#pragma unroll
    for (int kk = 0; kk < Kc; ++kk) lk[kk] = KEY_MAX;
    u64 worst = KEY_MAX;

    __syncthreads();

    // packed query norms: pairs (ti*4, ti*4+1), (ti*4+2, +3), (+128...)
    u64 xq[4];
    {
        ulonglong2 t0 = *(const ulonglong2*)&sxxi[ti * 4];
        ulonglong2 t1 = *(const ulonglong2*)&sxxi[128 + ti * 4];
        xq[0] = t0.x; xq[1] = t0.y; xq[2] = t1.x; xq[3] = t1.y;
    }
    const u64 neg2 = dup2(-2.f);

    for (int t = 0; t < Nc / TJ; ++t) {
        const int j0 = t * TJ;

        // load B tile global -> shared, duplicated for f32x2
        {
            int jc = (tid & 31) * 4;     // 4 j per thread
            int cb = tid >> 5;
#pragma unroll
            for (int cc = 0; cc < 4; ++cc) {
                int c = cb + cc * 16;
                float4 v = *(const float4*)&xb[(size_t)c * Nc + j0 + jc];
                u64* dst = (u64*)&Bs2[c * RP + jc * 2];
                dst[0] = dup2(v.x); dst[1] = dup2(v.y);
                dst[2] = dup2(v.z); dst[3] = dup2(v.w);
            }
        }
        if (tid < 128) sxxj[tid] = g_xx[b * Nc + j0 + tid];
        __syncthreads();   // B ready (also guards prev round-1 scan vs Bs2 rewrite)

        // ---- 8x8 f32x2 GEMM over c ----
        u64 acc[4][8];
#pragma unroll
        for (int ip = 0; ip < 4; ++ip)
#pragma unroll
            for (int j = 0; j < 8; ++j) acc[ip][j] = 0ULL;

#pragma unroll 4
        for (int c = 0; c < Cc; ++c) {
            ulonglong2 a0 = *(const ulonglong2*)&As[c * RP + ti * 4];
            ulonglong2 a1 = *(const ulonglong2*)&As[c * RP + 128 + ti * 4];
            const u64* brow = (const u64*)&Bs2[c * RP + tj * 16];
            ulonglong2 b01 = *(const ulonglong2*)&brow[0];
            ulonglong2 b23 = *(const ulonglong2*)&brow[2];
            ulonglong2 b45 = *(const ulonglong2*)&brow[4];
            ulonglong2 b67 = *(const ulonglong2*)&brow[6];
            u64 ap0 = a0.x, ap1 = a0.y, ap2 = a1.x, ap3 = a1.y;
            ffma2(acc[0][0], ap0, b01.x); ffma2(acc[1][0], ap1, b01.x);
            ffma2(acc[2][0], ap2, b01.x); ffma2(acc[3][0], ap3, b01.x);
            ffma2(acc[0][1], ap0, b01.y); ffma2(acc[1][1], ap1, b01.y);
            ffma2(acc[2][1], ap2, b01.y); ffma2(acc[3][1], ap3, b01.y);
            ffma2(acc[0][2], ap0, b23.x); ffma2(acc[1][2], ap1, b23.x);
            ffma2(acc[2][2], ap2, b23.x); ffma2(acc[3][2], ap3, b23.x);
            ffma2(acc[0][3], ap0, b23.y); ffma2(acc[1][3], ap1, b23.y);
            ffma2(acc[2][3], ap2, b23.y); ffma2(acc[3][3], ap3, b23.y);
            ffma2(acc[0][4], ap0, b45.x); ffma2(acc[1][4], ap1, b45.x);
            ffma2(acc[2][4], ap2, b45.x); ffma2(acc[3][4], ap3, b45.x);
            ffma2(acc[0][5], ap0, b45.y); ffma2(acc[1][5], ap1, b45.y);
            ffma2(acc[2][5], ap2, b45.y); ffma2(acc[3][5], ap3, b45.y);
            ffma2(acc[0][6], ap0, b67.x); ffma2(acc[1][6], ap1, b67.x);
            ffma2(acc[2][6], ap2, b67.x); ffma2(acc[3][6], ap3, b67.x);
            ffma2(acc[0][7], ap0, b67.y); ffma2(acc[1][7], ap1, b67.y);
            ffma2(acc[2][7], ap2, b67.y); ffma2(acc[3][7], ap3, b67.y);
        }

        // two rounds: store 64-j half into Ds, then all threads scan it
#pragma unroll
        for (int h = 0; h < 2; ++h) {
            if ((tj >> 3) == h) {
#pragma unroll
                for (int j = 0; j < 8; ++j) {
                    int row = (tj * 8 + j - h * 64) * RP;
                    u64 xjd = dup2(sxxj[tj * 8 + j]);
#pragma unroll
                    for (int ip = 0; ip < 4; ++ip) {
                        u64 pre = add2(xq[ip], xjd);
                        u64 d2  = fma2o(acc[ip][j], neg2, pre);
                        int icol = (ip < 2) ? (ti * 4 + 2 * ip)
                                            : (128 + ti * 4 + 2 * (ip - 2));
                        *(u64*)&Ds[row + icol] = d2;
                    }
                }
            }
            __syncthreads();   // half ready
            {
                const int jbase = j0 + h * 64 + qh * 32;
#pragma unroll 1
                for (int jj = 0; jj < 32; ++jj) {
                    float d = Ds[(qh * 32 + jj) * RP + qi];
                    u64 key = ((u64)ordf(d) << 32) | (u32)(jbase + jj);
                    if (key < worst) {
                        int p = Kc - 1;
                        while (p > 0) {
                            u64 v = lk[p - 1];
                            if (v < key) break;
                            lk[p] = v;
                            --p;
                        }
                        lk[p] = key;
                        worst = lk[Kc - 1];
                    }
                }
            }
            __syncthreads();   // scan done; Ds free for next half
        }
    }

    // dump local lists to shared (As/Bs2 space is dead now)
#pragma unroll
    for (int kk = 0; kk < Kc; ++kk) dump[kk * NT + tid] = lk[kk];
    __syncthreads();

    // merge the 2 half-lists per query (u64 order = dist, then idx)
    if (tid < 256) {
        u64 tk[Kc];
#pragma unroll
        for (int kk = 0; kk < Kc; ++kk) tk[kk] = KEY_MAX;
        for (int s = 0; s < 2; ++s) {
#pragma unroll 1
            for (int kk = 0; kk < Kc; ++kk) {
                u64 key = dump[kk * NT + s * 256 + tid];
                if (!(key < tk[Kc - 1])) break;   // source sorted ascending
                int p = Kc - 1;
                while (p > 0 && tk[p - 1] > key) {
                    tk[p] = tk[p - 1];
                    --p;
                }
                tk[p] = key;
            }
        }
        int* op = &g_idx[((size_t)(b * Nc + i0 + tid)) * Kc];
#pragma unroll
        for (int kk = 0; kk < Kc; ++kk) op[kk] = (int)(u32)(tk[kk] & 0xFFFFFFFFull);
    }
}

// -------------------- kernel: gather + max/min + BN stats --------------------
__global__ void __launch_bounds__(256) k_edge() {
    int o  = threadIdx.x & 63;
    int gg = threadIdx.x >> 6;
    float s1 = 0.f, s2v = 0.f;

    for (int row = blockIdx.x * 4 + gg; row < Bc * Nc; row += gridDim.x * 4) {
        int b  = row >> 12;
        int nb = b << 12;
        float qv = g_Q[(size_t)row * Oc + o];
        const int* ip = &g_idx[(size_t)row * Kc];
        float mx = -FLT_BIG, mn = FLT_BIG;
#pragma unroll
        for (int kk = 0; kk < Kc; ++kk) {
            int j = __ldg(&ip[kk]);
            float h = g_P[(size_t)(nb + j) * Oc + o] + qv;
            mx = fmaxf(mx, h);
            mn = fminf(mn, h);
            s1 += h;
            s2v = fmaf(h, h, s2v);
        }
        g_mx[(size_t)row * Oc + o] = mx;
        g_mn[(size_t)row * Oc + o] = mn;
    }

    __shared__ float sa[4][64], sb[4][64];
    sa[gg][o] = s1;
    sb[gg][o] = s2v;
    __syncthreads();
    if (gg == 0) {
        float t1 = sa[0][o] + sa[1][o] + sa[2][o] + sa[3][o];
        float t2 = sb[0][o] + sb[1][o] + sb[2][o] + sb[3][o];
        atomicAdd(&g_sum[o], (double)t1);
        atomicAdd(&g_sumsq[o], (double)t2);
    }
}

// -------------------- kernel: finalize BN affine --------------------
__global__ void k_fin(const float* __restrict__ gamma, const float* __restrict__ beta) {
    int o = threadIdx.x;
    const double cnt = (double)Bc * Nc * Kc;
    double mean = g_sum[o] / cnt;
    double var  = g_sumsq[o] / cnt - mean * mean;
    float a = gamma[o] * rsqrtf((float)var + BN_EPS);
    g_scale[o] = a;
    g_shift[o] = beta[o] - (float)mean * a;
}

// -------------------- kernel: apply affine + leaky + transpose to [B,O,N] --------------------
__global__ void __launch_bounds__(256) k_out(float* __restrict__ out) {
    int b  = blockIdx.y;
    int n0 = blockIdx.x * 64;
    __shared__ float sh[64][65];

    for (int t = threadIdx.x; t < 4096; t += 256) {
        int o  = t & 63;
        int nn = t >> 6;
        int row = b * Nc + n0 + nn;
        float a = g_scale[o];
        float m = (a >= 0.f) ? g_mx[(size_t)row * Oc + o] : g_mn[(size_t)row * Oc + o];
        float v = fmaf(a, m, g_shift[o]);
        v = (v >= 0.f) ? v : NEG_SLOPE * v;
        sh[o][nn] = v;
    }
    __syncthreads();
    for (int t = threadIdx.x; t < 4096; t += 256) {
        int nn = t & 63;
        int o  = t >> 6;
        out[((size_t)(b * Oc + o)) * Nc + n0 + nn] = sh[o][nn];
    }
}

// -------------------- launch --------------------
extern "C" void kernel_launch(void* const* d_in, const int* in_sizes, int n_in,
                              void* d_out, int out_size) {
    const float* x     = (const float*)d_in[0];   // [B, C, N]
    const float* W     = (const float*)d_in[1];   // [O, 2C]
    const float* gamma = (const float*)d_in[2];   // [O]
    const float* beta  = (const float*)d_in[3];   // [O]
    float* out = (float*)d_out;                   // [B, O, N]

    // As [Cc][RP] + Bs2 [Cc][RP] + Ds [64][RP] + sxxi[256] + sxxj[128]
    constexpr size_t KNN_SMEM =
        (size_t)(2 * Cc * RP + 64 * RP + 256 + 128) * 4;

    static bool attr_set = false;
    if (!attr_set) {
        cudaFuncSetAttribute(k_knn6, cudaFuncAttributeMaxDynamicSharedMemorySize,
                             (int)KNN_SMEM);
        attr_set = true;
    }

    k_xx<<<(Bc * Nc) / 256, 256>>>(x);
    k_prep<<<16, 256>>>(W);
    k_pq<<<dim3(Nc / 32, Bc), 256>>>(x);
    k_knn6<<<dim3(Nc / TI, Bc), NT, KNN_SMEM>>>(x);
    k_edge<<<512, 256>>>();
    k_fin<<<1, Oc>>>(gamma, beta);
    k_out<<<dim3(Nc / 64, Bc), 256>>>(out);
}

// round 8
// speedup vs baseline: 3.8830x; 3.8830x over previous
#include <cuda_runtime.h>
#include <math.h>

// Problem constants
constexpr int Bc = 8;
constexpr int Cc = 64;
constexpr int Nc = 4096;
constexpr int Kc = 20;
constexpr int Oc = 64;
constexpr float BN_EPS = 1e-5f;
constexpr float NEG_SLOPE = 0.2f;
constexpr float FLT_BIG = 3.4e38f;

constexpr int TI = 128;      // queries per block
constexpr int TJ = 128;      // candidate tile size
constexpr int APAD = 132;    // padded row stride for As/Ds (floats)
constexpr int BPAD = 260;    // padded row stride for duplicated B (floats)
constexpr int NT = 512;      // threads per block (knn)

// -------------------- device scratch (no allocations allowed) --------------------
__device__ float  g_xx[Bc * Nc];            // squared norms
__device__ int    g_idx[Bc * Nc * Kc];      // knn indices
__device__ float  g_P[Bc * Nc * Oc];        // W1 . x_j projection
__device__ float  g_Q[Bc * Nc * Oc];        // (W2-W1) . x_i projection
__device__ float  g_mx[Bc * Nc * Oc];       // max_k h
__device__ float  g_mn[Bc * Nc * Oc];       // min_k h
__device__ double g_sum[Oc];
__device__ double g_sumsq[Oc];
__device__ float  g_scale[Oc];
__device__ float  g_shift[Oc];
__device__ float  g_W1t[Cc * Oc];
__device__ float  g_Wdt[Cc * Oc];

// -------------------- f32x2 packed helpers --------------------
typedef unsigned long long u64;
typedef unsigned int u32;
__device__ __forceinline__ u64 dup2(float v) {
    u64 r; asm("mov.b64 %0, {%1, %1};" : "=l"(r) : "f"(v)); return r;
}
__device__ __forceinline__ void ffma2(u64& d, u64 a, u64 b) {
    asm("fma.rn.f32x2 %0, %1, %2, %0;" : "+l"(d) : "l"(a), "l"(b));
}
__device__ __forceinline__ u64 fma2o(u64 a, u64 b, u64 c) {
    u64 r; asm("fma.rn.f32x2 %0, %1, %2, %3;" : "=l"(r) : "l"(a), "l"(b), "l"(c));
    return r;
}
__device__ __forceinline__ u64 add2(u64 a, u64 b) {
    u64 r; asm("add.rn.f32x2 %0, %1, %2;" : "=l"(r) : "l"(a), "l"(b));
    return r;
}
// orderable float mapping: monotonic uint32 key (handles negatives)
__device__ __forceinline__ u32 ordf(float f) {
    u32 u = __float_as_uint(f);
    return (u & 0x80000000u) ? ~u : (u | 0x80000000u);
}

constexpr u64 KEY_MAX = 0xFFFFFFFFFFFFFFFFull;

// -------------------- kernel: squared norms --------------------
__global__ void k_xx(const float* __restrict__ x) {
    int t = blockIdx.x * blockDim.x + threadIdx.x;    // over B*N
    int b = t >> 12;
    int n = t & (Nc - 1);
    const float* xb = x + (size_t)b * Cc * Nc + n;
    float s = 0.f;
#pragma unroll
    for (int c = 0; c < Cc; ++c) {
        float v = xb[c * Nc];
        s = fmaf(v, v, s);
    }
    g_xx[t] = s;
}

// -------------------- kernel: prep W transposes + zero stats --------------------
__global__ void k_prep(const float* __restrict__ W) {
    int t = blockIdx.x * blockDim.x + threadIdx.x;
    if (t < Cc * Oc) {
        int c = t & 63;
        int o = t >> 6;
        float w1 = W[o * (2 * Cc) + c];
        float w2 = W[o * (2 * Cc) + Cc + c];
        g_W1t[c * Oc + o] = w1;
        g_Wdt[c * Oc + o] = w2 - w1;
    }
    if (blockIdx.x == 0 && t < Oc) {
        g_sum[t] = 0.0;
        g_sumsq[t] = 0.0;
    }
}

// -------------------- kernel: P and Q projections --------------------
__global__ void __launch_bounds__(256) k_pq(const float* __restrict__ x) {
    int b  = blockIdx.y;
    int n0 = blockIdx.x * 32;
    int o  = threadIdx.x & 63;
    int gg = threadIdx.x >> 6;
    __shared__ float xs[Cc][36];

    for (int t = threadIdx.x; t < Cc * 32; t += 256) {
        int nn = t & 31;
        int c  = t >> 5;
        xs[c][nn] = x[(size_t)b * Cc * Nc + c * Nc + n0 + nn];
    }
    __syncthreads();

    float ap[8], aq[8];
#pragma unroll
    for (int r = 0; r < 8; ++r) { ap[r] = 0.f; aq[r] = 0.f; }
    const int nbase = gg * 8;

#pragma unroll 8
    for (int c = 0; c < Cc; ++c) {
        float w1 = __ldg(&g_W1t[c * Oc + o]);
        float wd = __ldg(&g_Wdt[c * Oc + o]);
        float4 v0 = *(const float4*)&xs[c][nbase];
        float4 v1 = *(const float4*)&xs[c][nbase + 4];
        ap[0] = fmaf(w1, v0.x, ap[0]); aq[0] = fmaf(wd, v0.x, aq[0]);
        ap[1] = fmaf(w1, v0.y, ap[1]); aq[1] = fmaf(wd, v0.y, aq[1]);
        ap[2] = fmaf(w1, v0.z, ap[2]); aq[2] = fmaf(wd, v0.z, aq[2]);
        ap[3] = fmaf(w1, v0.w, ap[3]); aq[3] = fmaf(wd, v0.w, aq[3]);
        ap[4] = fmaf(w1, v1.x, ap[4]); aq[4] = fmaf(wd, v1.x, aq[4]);
        ap[5] = fmaf(w1, v1.y, ap[5]); aq[5] = fmaf(wd, v1.y, aq[5]);
        ap[6] = fmaf(w1, v1.z, ap[6]); aq[6] = fmaf(wd, v1.z, aq[6]);
        ap[7] = fmaf(w1, v1.w, ap[7]); aq[7] = fmaf(wd, v1.w, aq[7]);
    }

    int row0 = b * Nc + n0 + nbase;
#pragma unroll
    for (int r = 0; r < 8; ++r) {
        g_P[(size_t)(row0 + r) * Oc + o] = ap[r];
        g_Q[(size_t)(row0 + r) * Oc + o] = aq[r];
    }
}

// -------------------- kernel: GEMM-tiled KNN v7 --------------------
// grid = (N/128, B) = 256 blocks, block = 512, smem ~212 KB (1 block/SM).
// Block tile 128i x 128j; thread (ti=tid&31, tj=tid>>5) owns 4i x 8j.
// B is stored DUPLICATED as f32x2 in Bs2 (loader maps j = lane + 32*jj so the
// STS.64 lane stride is 8B -> natural 2 wavefronts, no 8-way conflicts), so
// the GEMM inner loop is 16 FFMA2 + 5 LDS.128 with ZERO dup-MOVs.
// Distances go through Ds[64][APAD] in two halves per tile; top-K lists are
// u64 keys (ord(dist)<<32|idx) in SHARED (scan thread: qi=tid&127, qq=tid>>7
// handles 16 j per half). Final 4-way merge per query -> g_idx.
__global__ void __launch_bounds__(NT) k_knn7(const float* __restrict__ x) {
    extern __shared__ float sm[];
    u64*   keys = (u64*)sm;                      // [Kc][NT]
    float* As   = sm + Kc * NT * 2;              // [Cc][APAD]
    float* Bs2  = As + Cc * APAD;                // [Cc][BPAD] (dup'd, 256 cols)
    float* Ds   = Bs2 + Cc * BPAD;               // [64][APAD]
    float* sxxi = Ds + 64 * APAD;                // [128]
    float* sxxj = sxxi + 128;                    // [128]

    const int tid = threadIdx.x;
    const int b   = blockIdx.y;
    const int i0  = blockIdx.x * TI;
    const float* xb = x + (size_t)b * Cc * Nc;

    const int ti = tid & 31;      // i-group (4 queries)
    const int tj = tid >> 5;      // j-group (8 candidates), warp-uniform
    const int qi = tid & 127;     // scan query
    const int qq = tid >> 7;      // scan quarter (0..3)

    // load A tile: As[c][ii] = x[b][c][i0+ii]
    {
        int col = (tid & 31) * 4;
        int cb  = tid >> 5;
#pragma unroll
        for (int cc = 0; cc < 4; ++cc) {
            int c = cb + cc * 16;
            float4 v = *(const float4*)&xb[(size_t)c * Nc + i0 + col];
            *(float4*)&As[c * APAD + col] = v;
        }
    }
    if (tid < 128) sxxi[tid] = g_xx[b * Nc + i0 + tid];
#pragma unroll
    for (int kk = 0; kk < Kc; ++kk) keys[kk * NT + tid] = KEY_MAX;
    __syncthreads();

    // packed query norms for this thread's 2 i-pairs
    u64 xq[2];
    {
        ulonglong2 t0 = *(const ulonglong2*)&sxxi[ti * 4];
        xq[0] = t0.x; xq[1] = t0.y;
    }
    const u64 neg2 = dup2(-2.f);
    u64 worst = KEY_MAX;

    for (int t = 0; t < Nc / TJ; ++t) {
        const int j0 = t * TJ;

        // load B tile global -> shared, duplicated for f32x2.
        // lane = tid&31 -> j base; 4 j per thread at stride 32 (8B STS stride).
        {
            int lane = tid & 31;
            int cb   = tid >> 5;       // 16 c-groups
#pragma unroll
            for (int cc = 0; cc < 4; ++cc) {
                int c = cb + cc * 16;
                const float* src = &xb[(size_t)c * Nc + j0 + lane];
                u64* drow = (u64*)&Bs2[c * BPAD];
#pragma unroll
                for (int jj = 0; jj < 4; ++jj) {
                    drow[lane + 32 * jj] = dup2(src[32 * jj]);
                }
            }
        }
        if (tid < 128) sxxj[tid] = g_xx[b * Nc + j0 + tid];
        __syncthreads();   // B ready (also guards prev half-1 scan vs Bs2 reuse)

        // ---- 4i x 8j f32x2 GEMM over c: 16 FFMA2 + 5 LDS.128, no MOVs ----
        u64 acc[2][8];
#pragma unroll
        for (int ip = 0; ip < 2; ++ip)
#pragma unroll
            for (int j = 0; j < 8; ++j) acc[ip][j] = 0ULL;

#pragma unroll 4
        for (int c = 0; c < Cc; ++c) {
            ulonglong2 a0 = *(const ulonglong2*)&As[c * APAD + ti * 4];
            const u64* brow = (const u64*)&Bs2[c * BPAD] + tj * 8;
            ulonglong2 b01 = *(const ulonglong2*)&brow[0];
            ulonglong2 b23 = *(const ulonglong2*)&brow[2];
            ulonglong2 b45 = *(const ulonglong2*)&brow[4];
            ulonglong2 b67 = *(const ulonglong2*)&brow[6];
            u64 ap0 = a0.x, ap1 = a0.y;
            ffma2(acc[0][0], ap0, b01.x); ffma2(acc[1][0], ap1, b01.x);
            ffma2(acc[0][1], ap0, b01.y); ffma2(acc[1][1], ap1, b01.y);
            ffma2(acc[0][2], ap0, b23.x); ffma2(acc[1][2], ap1, b23.x);
            ffma2(acc[0][3], ap0, b23.y); ffma2(acc[1][3], ap1, b23.y);
            ffma2(acc[0][4], ap0, b45.x); ffma2(acc[1][4], ap1, b45.x);
            ffma2(acc[0][5], ap0, b45.y); ffma2(acc[1][5], ap1, b45.y);
            ffma2(acc[0][6], ap0, b67.x); ffma2(acc[1][6], ap1, b67.x);
            ffma2(acc[0][7], ap0, b67.y); ffma2(acc[1][7], ap1, b67.y);
        }

        // two halves: store 64-j half into Ds, then all 512 threads scan it
#pragma unroll
        for (int h = 0; h < 2; ++h) {
            if ((tj >> 3) == h) {
#pragma unroll
                for (int j = 0; j < 8; ++j) {
                    int row = (tj * 8 + j - h * 64) * APAD;
                    u64 xjd = dup2(sxxj[tj * 8 + j]);
                    u64 d0 = fma2o(acc[0][j], neg2, add2(xq[0], xjd));
                    u64 d1 = fma2o(acc[1][j], neg2, add2(xq[1], xjd));
                    *(u64*)&Ds[row + ti * 4]     = d0;
                    *(u64*)&Ds[row + ti * 4 + 2] = d1;
                }
            }
            __syncthreads();   // half ready
            {
                const int jbase = j0 + h * 64 + qq * 16;
#pragma unroll 1
                for (int jj = 0; jj < 16; ++jj) {
                    float d = Ds[(qq * 16 + jj) * APAD + qi];
                    u64 key = ((u64)ordf(d) << 32) | (u32)(jbase + jj);
                    if (key < worst) {
                        int p = Kc - 1;
                        while (p > 0) {
                            u64 v = keys[(p - 1) * NT + tid];
                            if (v < key) break;
                            keys[p * NT + tid] = v;
                            --p;
                        }
                        keys[p * NT + tid] = key;
                        worst = keys[(Kc - 1) * NT + tid];
                    }
                }
            }
            __syncthreads();   // scan done; Ds free for next half
        }
    }

    // merge the 4 quarter lists per query (u64 order = dist, then idx)
    if (tid < 128) {
        u64 tk[Kc];
#pragma unroll
        for (int kk = 0; kk < Kc; ++kk) tk[kk] = KEY_MAX;
        for (int s = 0; s < 4; ++s) {
#pragma unroll 1
            for (int kk = 0; kk < Kc; ++kk) {
                u64 key = keys[kk * NT + s * 128 + tid];
                if (!(key < tk[Kc - 1])) break;   // source sorted ascending
                int p = Kc - 1;
                while (p > 0 && tk[p - 1] > key) {
                    tk[p] = tk[p - 1];
                    --p;
                }
                tk[p] = key;
            }
        }
        int* op = &g_idx[((size_t)(b * Nc + i0 + tid)) * Kc];
#pragma unroll
        for (int kk = 0; kk < Kc; ++kk) op[kk] = (int)(u32)(tk[kk] & 0xFFFFFFFFull);
    }
}

// -------------------- kernel: gather + max/min + BN stats --------------------
__global__ void __launch_bounds__(256) k_edge() {
    int o  = threadIdx.x & 63;
    int gg = threadIdx.x >> 6;
    float s1 = 0.f, s2v = 0.f;

    for (int row = blockIdx.x * 4 + gg; row < Bc * Nc; row += gridDim.x * 4) {
        int b  = row >> 12;
        int nb = b << 12;
        float qv = g_Q[(size_t)row * Oc + o];
        const int* ip = &g_idx[(size_t)row * Kc];
        float mx = -FLT_BIG, mn = FLT_BIG;
#pragma unroll
        for (int kk = 0; kk < Kc; ++kk) {
            int j = __ldg(&ip[kk]);
            float h = g_P[(size_t)(nb + j) * Oc + o] + qv;
            mx = fmaxf(mx, h);
            mn = fminf(mn, h);
            s1 += h;
            s2v = fmaf(h, h, s2v);
        }
        g_mx[(size_t)row * Oc + o] = mx;
        g_mn[(size_t)row * Oc + o] = mn;
    }

    __shared__ float sa[4][64], sb[4][64];
    sa[gg][o] = s1;
    sb[gg][o] = s2v;
    __syncthreads();
    if (gg == 0) {
        float t1 = sa[0][o] + sa[1][o] + sa[2][o] + sa[3][o];
        float t2 = sb[0][o] + sb[1][o] + sb[2][o] + sb[3][o];
        atomicAdd(&g_sum[o], (double)t1);
        atomicAdd(&g_sumsq[o], (double)t2);
    }
}

// -------------------- kernel: finalize BN affine --------------------
__global__ void k_fin(const float* __restrict__ gamma, const float* __restrict__ beta) {
    int o = threadIdx.x;
    const double cnt = (double)Bc * Nc * Kc;
    double mean = g_sum[o] / cnt;
    double var  = g_sumsq[o] / cnt - mean * mean;
    float a = gamma[o] * rsqrtf((float)var + BN_EPS);
    g_scale[o] = a;
    g_shift[o] = beta[o] - (float)mean * a;
}

// -------------------- kernel: apply affine + leaky + transpose to [B,O,N] --------------------
__global__ void __launch_bounds__(256) k_out(float* __restrict__ out) {
    int b  = blockIdx.y;
    int n0 = blockIdx.x * 64;
    __shared__ float sh[64][65];

    for (int t = threadIdx.x; t < 4096; t += 256) {
        int o  = t & 63;
        int nn = t >> 6;
        int row = b * Nc + n0 + nn;
        float a = g_scale[o];
        float m = (a >= 0.f) ? g_mx[(size_t)row * Oc + o] : g_mn[(size_t)row * Oc + o];
        float v = fmaf(a, m, g_shift[o]);
        v = (v >= 0.f) ? v : NEG_SLOPE * v;
        sh[o][nn] = v;
    }
    __syncthreads();
    for (int t = threadIdx.x; t < 4096; t += 256) {
        int nn = t & 63;
        int o  = t >> 6;
        out[((size_t)(b * Oc + o)) * Nc + n0 + nn] = sh[o][nn];
    }
}

// -------------------- launch --------------------
extern "C" void kernel_launch(void* const* d_in, const int* in_sizes, int n_in,
                              void* d_out, int out_size) {
    const float* x     = (const float*)d_in[0];   // [B, C, N]
    const float* W     = (const float*)d_in[1];   // [O, 2C]
    const float* gamma = (const float*)d_in[2];   // [O]
    const float* beta  = (const float*)d_in[3];   // [O]
    float* out = (float*)d_out;                   // [B, O, N]

    // keys[Kc][NT] u64 + As[Cc][APAD] + Bs2[Cc][BPAD] + Ds[64][APAD] + sxx
    constexpr size_t KNN_SMEM =
        (size_t)(Kc * NT * 2 + Cc * APAD + Cc * BPAD + 64 * APAD + 256) * 4;

    static bool attr_set = false;
    if (!attr_set) {
        cudaFuncSetAttribute(k_knn7, cudaFuncAttributeMaxDynamicSharedMemorySize,
                             (int)KNN_SMEM);
        attr_set = true;
    }

    k_xx<<<(Bc * Nc) / 256, 256>>>(x);
    k_prep<<<16, 256>>>(W);
    k_pq<<<dim3(Nc / 32, Bc), 256>>>(x);
    k_knn7<<<dim3(Nc / TI, Bc), NT, KNN_SMEM>>>(x);
    k_edge<<<512, 256>>>();
    k_fin<<<1, Oc>>>(gamma, beta);
    k_out<<<dim3(Nc / 64, Bc), 256>>>(out);
}